// round 16
// baseline (speedup 1.0000x reference)
#include <cuda_runtime.h>
#include <cuda_fp16.h>
#include <stdint.h>

#define N_ENT 4096
#define FDIM  512
#define CELLS 39
#define PAIRS 8192

// ---------------- scratch (device globals: allocation-free rule) ----------------
__device__ __half g_Eh[N_ENT * FDIM];                       // 4 MB   fp16(E)
__device__ __half g_Bh[(size_t)CELLS * FDIM * FDIM];        // 20 MB  fp16(wl*W*2^10) [c][kout][n]
__device__ __half g_T[(size_t)CELLS * N_ENT * FDIM];        // 163 MB fp16( T'_c * 2^6 ), compacted rows
__device__ int    g_list[CELLS * N_ENT];                    // compact row -> entity id
__device__ int    g_map[CELLS * N_ENT];                     // entity id -> compact row
__device__ int    g_cnt[CELLS];                             // distinct i0 count per cell

// ---------------- small helpers ----------------
__device__ __forceinline__ uint32_t smem_to_u32(const void* p) {
    uint32_t a;
    asm("{ .reg .u64 t; cvta.to.shared.u64 t, %1; cvt.u32.u64 %0, t; }" : "=r"(a) : "l"(p));
    return a;
}
__device__ __forceinline__ void cp_async16(uint32_t dst, const void* src) {
    asm volatile("cp.async.cg.shared.global [%0], [%1], 16;" :: "r"(dst), "l"(src));
}
#define CP_COMMIT() asm volatile("cp.async.commit_group;" ::: "memory")
#define CP_WAIT(n)  asm volatile("cp.async.wait_group %0;" :: "n"(n) : "memory")

#define LDSM_X4(r, addr) \
    asm volatile("ldmatrix.sync.aligned.m8n8.x4.shared.b16 {%0,%1,%2,%3}, [%4];" \
        : "=r"((r)[0]), "=r"((r)[1]), "=r"((r)[2]), "=r"((r)[3]) : "r"(addr))

__device__ __forceinline__ void mma_f16(float* c, const uint32_t* a, uint32_t b0, uint32_t b1) {
    asm volatile("mma.sync.aligned.m16n8k16.row.col.f32.f16.f16.f32 "
                 "{%0,%1,%2,%3}, {%4,%5,%6,%7}, {%8,%9}, {%0,%1,%2,%3};"
                 : "+f"(c[0]), "+f"(c[1]), "+f"(c[2]), "+f"(c[3])
                 : "r"(a[0]), "r"(a[1]), "r"(a[2]), "r"(a[3]), "r"(b0), "r"(b1));
}

// ---------------- prep kernels ----------------
__global__ void prep_E(const float* __restrict__ emb) {
    for (int i = blockIdx.x * blockDim.x + threadIdx.x; i < N_ENT * FDIM; i += gridDim.x * blockDim.x)
        g_Eh[i] = __float2half(emb[i]);
}

// Bh = fp16( wl[c,n]*W[n,kout]*1024 )  — transpose via smem tile
__global__ void prep_B(const float* __restrict__ W, const float* __restrict__ wl) {
    __shared__ float sW[32][33];
    int tx = threadIdx.x, ty = threadIdx.y;
    int n0 = blockIdx.x * 32, k0 = blockIdx.y * 32;
    sW[ty][tx] = W[(n0 + ty) * FDIM + (k0 + tx)];
    __syncthreads();
    float wv = sW[tx][ty];
    int oidx = (k0 + ty) * FDIM + (n0 + tx);
    for (int c = 0; c < CELLS; c++) {
        float v = 1024.f * wl[c * FDIM + n0 + tx] * wv;
        g_Bh[(size_t)c * FDIM * FDIM + oidx] = __float2half(v);
    }
}

// per-cell distinct-i0 compaction: flags + block scan. One block per cell, 1024 threads.
__global__ void __launch_bounds__(1024) compact_kernel(const int* __restrict__ index) {
    int c = blockIdx.x, t = threadIdx.x;
    __shared__ unsigned char flags[N_ENT];
    __shared__ int wsum[32];
    #pragma unroll
    for (int i = t; i < N_ENT; i += 1024) flags[i] = 0;
    __syncthreads();
    for (int p = t; p < PAIRS; p += 1024)
        flags[index[((size_t)c * PAIRS + p) * 2]] = 1;  // races benign (same value)
    __syncthreads();
    int f[4], s = 0;
    #pragma unroll
    for (int j = 0; j < 4; j++) { f[j] = flags[t * 4 + j]; s += f[j]; }
    int lane = t & 31, wid = t >> 5;
    int sc = s;
    #pragma unroll
    for (int o = 1; o < 32; o <<= 1) {
        int v = __shfl_up_sync(0xffffffffu, sc, o);
        if (lane >= o) sc += v;
    }
    if (lane == 31) wsum[wid] = sc;
    __syncthreads();
    if (wid == 0) {
        int v = wsum[lane];
        #pragma unroll
        for (int o = 1; o < 32; o <<= 1) {
            int u = __shfl_up_sync(0xffffffffu, v, o);
            if (lane >= o) v += u;
        }
        wsum[lane] = v;   // inclusive scan of warp totals
    }
    __syncthreads();
    int base = (wid > 0 ? wsum[wid - 1] : 0) + (sc - s);   // exclusive prefix
    #pragma unroll
    for (int j = 0; j < 4; j++) {
        if (f[j]) {
            int i = t * 4 + j;
            g_map[c * N_ENT + i] = base;
            g_list[c * N_ENT + base] = i;
            base++;
        }
    }
    if (t == 1023) g_cnt[c] = wsum[31];
}

// ---------------- GEMM: compacted-M fp16, XOR-swizzled smem, 2 CTAs/SM, 3-stage ---------
// CTA tile M=128, N=128, BK=64, 256 threads (8 warps 2Mx4N, warp tile 64x32).
// Runs at the measured structural HMMA rate (~13-14 cyc/mma/SMSP).
#define BK          64
#define NKC         (FDIM / BK)       // 8 chunks
#define A_TILE      (128 * 128)       // 16384
#define B_TILE      (128 * 128)       // 16384
#define A_OFF       0
#define B_OFF       (A_TILE)
#define BUF_BYTES   (A_TILE + B_TILE)       // 32768
#define NSTAGE      3
#define GEMM_SMEM   (NSTAGE * BUF_BYTES)    // 98304 -> 2 CTAs/SM
#define NTHREADS    256

__device__ __forceinline__ void load_buf(uint32_t smem_u, int stage, int kc, int tid,
                                         const int* srow, const char* bh) {
    uint32_t dbase = smem_u + stage * BUF_BYTES;
    #pragma unroll
    for (int i = 0; i < 4; i++) {
        int v = i * NTHREADS + tid;
        int row = v >> 3, seg = v & 7;
        const char* s = (const char*)g_Eh + (size_t)srow[row] * (FDIM * 2)
                        + (size_t)kc * (BK * 2) + seg * 16;
        cp_async16(dbase + A_OFF + row * 128 + ((seg ^ (row & 7)) << 4), s);
    }
    {
        const char* s = bh + (size_t)kc * (BK * 2);
        #pragma unroll
        for (int i = 0; i < 4; i++) {
            int v = i * NTHREADS + tid;
            int row = v >> 3, seg = v & 7;
            cp_async16(dbase + B_OFF + row * 128 + ((seg ^ (row & 7)) << 4),
                       s + (size_t)row * (FDIM * 2) + seg * 16);
        }
    }
}

__global__ void __launch_bounds__(NTHREADS, 2)
gemm_kernel(const float* __restrict__ wl, int c0) {
    extern __shared__ char smem[];
    __shared__ int srow[128];
    uint32_t smem_u = smem_to_u32(smem);

    const int tid = threadIdx.x;
    const int wid = tid >> 5, lane = tid & 31;
    const int warp_m = wid & 1;
    const int warp_n = wid >> 1;
    const int mt = blockIdx.x, nt = blockIdx.y, c = blockIdx.z + c0;

    const int cnt = __ldg(&g_cnt[c]);
    if (mt * 128 >= cnt) return;

    if (tid < 128) {
        int r = mt * 128 + tid;
        srow[tid] = __ldg(&g_list[c * N_ENT + (r < cnt ? r : mt * 128)]);
    }
    __syncthreads();

    const char* bh = (const char*)g_Bh + ((size_t)c * FDIM + nt * 128) * (FDIM * 2);

    float acc[4][4][4];
    #pragma unroll
    for (int i = 0; i < 4; i++)
        #pragma unroll
        for (int j = 0; j < 4; j++)
            #pragma unroll
            for (int q = 0; q < 4; q++) acc[i][j][q] = 0.f;

    const int lr = lane & 15;
    const int hsel = lane >> 4;
    const int sw = lr & 7;

    load_buf(smem_u, 0, 0, tid, srow, bh);
    CP_COMMIT();
    load_buf(smem_u, 1, 1, tid, srow, bh);
    CP_COMMIT();

    int stage = 0;
    for (int kc = 0; kc < NKC; kc++) {
        CP_WAIT(1);
        __syncthreads();
        if (kc + 2 < NKC) {
            int s2 = stage + 2; if (s2 >= NSTAGE) s2 -= NSTAGE;
            load_buf(smem_u, s2, kc + 2, tid, srow, bh);
            CP_COMMIT();
        } else {
            CP_COMMIT();
        }

        uint32_t base = smem_u + stage * BUF_BYTES;
        uint32_t aBase = base + A_OFF + (warp_m * 64 + lr) * 128;
        uint32_t bBase = base + B_OFF + (warp_n * 32 + lr) * 128;

        #pragma unroll
        for (int k16 = 0; k16 < BK / 16; k16++) {
            uint32_t cc = (uint32_t)(((k16 * 2 + hsel) ^ sw) << 4);
            uint32_t ah[4][4], bf[2][4];
            #pragma unroll
            for (int mi = 0; mi < 4; mi++)
                LDSM_X4(ah[mi], aBase + mi * (16 * 128) + cc);
            #pragma unroll
            for (int nj = 0; nj < 2; nj++)
                LDSM_X4(bf[nj], bBase + nj * (16 * 128) + cc);
            #pragma unroll
            for (int mi = 0; mi < 4; mi++)
                #pragma unroll
                for (int n = 0; n < 4; n++) {
                    int nj = n >> 1, hf = n & 1;
                    mma_f16(acc[mi][n], ah[mi], bf[nj][hf], bf[nj][hf + 2]);
                }
        }
        if (++stage >= NSTAGE) stage = 0;
    }

    // epilogue: T16[compact row] = fp16( acc * 2^-10 * wl[c,kout] * 2^6 )
    const int gid = lane >> 2, tq = lane & 3;
    const int row0 = mt * 128 + warp_m * 64 + gid;
    const int col0 = nt * 128 + warp_n * 32 + tq * 2;
    const float s_main = 64.0f / 1024.0f;
    #pragma unroll
    for (int n = 0; n < 4; n++) {
        int cg = col0 + n * 8;
        float w0 = __ldg(&wl[c * FDIM + cg]) * s_main;
        float w1 = __ldg(&wl[c * FDIM + cg + 1]) * s_main;
        #pragma unroll
        for (int mi = 0; mi < 4; mi++) {
            int r = row0 + mi * 16;
            __half* o0 = g_T + ((size_t)c * N_ENT + r) * FDIM + cg;
            __half* o1 = g_T + ((size_t)c * N_ENT + r + 8) * FDIM + cg;
            *(__half2*)o0 = __floats2half2_rn(acc[mi][n][0] * w0, acc[mi][n][1] * w1);
            *(__half2*)o1 = __floats2half2_rn(acc[mi][n][2] * w0, acc[mi][n][3] * w1);
        }
    }
}

// ---------------- gather-dot: out[c,p] = 2^-6 * dot(T16_c[map[i0],:], Eh[i1,:]) ---------
__global__ void __launch_bounds__(256) gather_kernel(const int* __restrict__ index,
                                                     float* __restrict__ out, int c0) {
    int gw = (blockIdx.x * blockDim.x + threadIdx.x) >> 5;
    int lane = threadIdx.x & 31;
    int p0 = gw * 4;
    int c = p0 / PAIRS + c0, p = p0 % PAIRS;
    const uint4* ta[4];
    const uint4* tb[4];
    #pragma unroll
    for (int u = 0; u < 4; u++) {
        int2 ip = __ldg((const int2*)index + (size_t)c * PAIRS + p + u);
        int r0 = __ldg(&g_map[c * N_ENT + ip.x]);
        ta[u] = (const uint4*)(g_T + ((size_t)c * N_ENT + r0) * FDIM);
        tb[u] = (const uint4*)(g_Eh + (size_t)ip.y * FDIM);
    }
    float acc[4] = {0.f, 0.f, 0.f, 0.f};
    #pragma unroll
    for (int j = 0; j < 2; j++) {
        #pragma unroll
        for (int u = 0; u < 4; u++) {
            uint4 x = __ldg(ta[u] + lane + j * 32);
            uint4 y = __ldg(tb[u] + lane + j * 32);
            const uint32_t* xa = (const uint32_t*)&x;
            const uint32_t* ya = (const uint32_t*)&y;
            #pragma unroll
            for (int q = 0; q < 4; q++) {
                float2 fx = __half22float2(*(const __half2*)&xa[q]);
                float2 fy = __half22float2(*(const __half2*)&ya[q]);
                acc[u] += fx.x * fy.x + fx.y * fy.y;
            }
        }
    }
    #pragma unroll
    for (int o = 16; o; o >>= 1)
        #pragma unroll
        for (int u = 0; u < 4; u++)
            acc[u] += __shfl_xor_sync(0xffffffffu, acc[u], o);
    if (lane == 0) {
        const float s = 1.0f / 64.0f;
        #pragma unroll
        for (int u = 0; u < 4; u++)
            out[(size_t)c * PAIRS + p + u] = acc[u] * s;
    }
}

// ---------------- launch: 3 serialized gemm groups (16/16/7 cells); gathers overlap ------
#define NGROUP 3

extern "C" void kernel_launch(void* const* d_in, const int* in_sizes, int n_in,
                              void* d_out, int out_size) {
    const float* emb   = (const float*)d_in[0];   // [4096, 512] f32
    const int*   index = (const int*)d_in[1];     // [39, 8192, 2] i32
    const float* W     = (const float*)d_in[2];   // [512, 512] f32
    const float* wl    = (const float*)d_in[3];   // [39, 512] f32
    float* out = (float*)d_out;                   // [39, 8192] f32

    static cudaStream_t sA = nullptr, sB = nullptr, sG = nullptr;
    static cudaEvent_t evFork, evPrepB, evCmp;
    static cudaEvent_t evGemm[NGROUP], evJA, evJG;
    if (sA == nullptr) {
        cudaStreamCreateWithFlags(&sA, cudaStreamNonBlocking);
        cudaStreamCreateWithFlags(&sB, cudaStreamNonBlocking);
        cudaStreamCreateWithFlags(&sG, cudaStreamNonBlocking);
        cudaEventCreateWithFlags(&evFork, cudaEventDisableTiming);
        cudaEventCreateWithFlags(&evPrepB, cudaEventDisableTiming);
        cudaEventCreateWithFlags(&evCmp, cudaEventDisableTiming);
        for (int g = 0; g < NGROUP; g++)
            cudaEventCreateWithFlags(&evGemm[g], cudaEventDisableTiming);
        cudaEventCreateWithFlags(&evJA, cudaEventDisableTiming);
        cudaEventCreateWithFlags(&evJG, cudaEventDisableTiming);
        cudaFuncSetAttribute(gemm_kernel, cudaFuncAttributeMaxDynamicSharedMemorySize, GEMM_SMEM);
    }

    // Fork side streams from the capture (default) stream.
    cudaEventRecord(evFork, 0);
    cudaStreamWaitEvent(sA, evFork, 0);
    cudaStreamWaitEvent(sB, evFork, 0);
    cudaStreamWaitEvent(sG, evFork, 0);

    // Preps run concurrently: prep_E on sA (gemm stream — ordering free),
    // prep_B on sB, compact on sG.
    prep_E<<<1024, 256, 0, sA>>>(emb);
    prep_B<<<dim3(FDIM / 32, FDIM / 32), dim3(32, 32), 0, sB>>>(W, wl);
    cudaEventRecord(evPrepB, sB);
    compact_kernel<<<CELLS, 1024, 0, sG>>>(index);
    cudaEventRecord(evCmp, sG);

    // Gemm stream needs prep_B and compact (prep_E already ordered on sA).
    cudaStreamWaitEvent(sA, evPrepB, 0);
    cudaStreamWaitEvent(sA, evCmp, 0);

    // 3 serialized gemm groups on sA (16/16/7 cells — smallest LAST so only the
    // smallest gather is exposed). Gathers on sG backfill gemm partial waves.
    const int gsize[NGROUP] = {16, 16, CELLS - 32};   // 16,16,7
    int c0 = 0;
    for (int g = 0; g < NGROUP; g++) {
        int nc = gsize[g];
        gemm_kernel<<<dim3(N_ENT / 128, FDIM / 128, nc), NTHREADS, GEMM_SMEM, sA>>>(wl, c0);
        cudaEventRecord(evGemm[g], sA);
        cudaStreamWaitEvent(sG, evGemm[g], 0);
        gather_kernel<<<nc * (PAIRS / 32), 256, 0, sG>>>(index, out, c0);
        c0 += nc;
    }

    // Rejoin onto the capture stream (sB already feeds sA via evPrepB).
    cudaEventRecord(evJA, sA); cudaStreamWaitEvent(0, evJA, 0);
    cudaEventRecord(evJG, sG); cudaStreamWaitEvent(0, evJG, 0);
}

// round 17
// speedup vs baseline: 1.0546x; 1.0546x over previous
#include <cuda_runtime.h>
#include <cuda_fp16.h>
#include <stdint.h>

#define N_ENT 4096
#define FDIM  512
#define CELLS 39
#define PAIRS 8192

// ---------------- scratch (device globals: allocation-free rule) ----------------
__device__ __half g_Eh[N_ENT * FDIM];                       // 4 MB   fp16(E)
__device__ __half g_Bh[(size_t)CELLS * FDIM * FDIM];        // 20 MB  fp16(wl*W*2^10) [c][kout][n]
__device__ __half g_T[(size_t)CELLS * N_ENT * FDIM];        // 163 MB fp16( T'_c * 2^6 ), compacted rows
__device__ int    g_list[CELLS * N_ENT];                    // compact row -> entity id
__device__ int    g_map[CELLS * N_ENT];                     // entity id -> compact row
__device__ int    g_cnt[CELLS];                             // distinct i0 count per cell

// ---------------- small helpers ----------------
__device__ __forceinline__ uint32_t smem_to_u32(const void* p) {
    uint32_t a;
    asm("{ .reg .u64 t; cvta.to.shared.u64 t, %1; cvt.u32.u64 %0, t; }" : "=r"(a) : "l"(p));
    return a;
}
__device__ __forceinline__ void cp_async16(uint32_t dst, const void* src) {
    asm volatile("cp.async.cg.shared.global [%0], [%1], 16;" :: "r"(dst), "l"(src));
}
#define CP_COMMIT() asm volatile("cp.async.commit_group;" ::: "memory")
#define CP_WAIT(n)  asm volatile("cp.async.wait_group %0;" :: "n"(n) : "memory")

#define LDSM_X4(r, addr) \
    asm volatile("ldmatrix.sync.aligned.m8n8.x4.shared.b16 {%0,%1,%2,%3}, [%4];" \
        : "=r"((r)[0]), "=r"((r)[1]), "=r"((r)[2]), "=r"((r)[3]) : "r"(addr))

__device__ __forceinline__ void mma_f16(float* c, const uint32_t* a, uint32_t b0, uint32_t b1) {
    asm volatile("mma.sync.aligned.m16n8k16.row.col.f32.f16.f16.f32 "
                 "{%0,%1,%2,%3}, {%4,%5,%6,%7}, {%8,%9}, {%0,%1,%2,%3};"
                 : "+f"(c[0]), "+f"(c[1]), "+f"(c[2]), "+f"(c[3])
                 : "r"(a[0]), "r"(a[1]), "r"(a[2]), "r"(a[3]), "r"(b0), "r"(b1));
}

// ---------------- prep kernels ----------------
__global__ void prep_E(const float* __restrict__ emb) {
    for (int i = blockIdx.x * blockDim.x + threadIdx.x; i < N_ENT * FDIM; i += gridDim.x * blockDim.x)
        g_Eh[i] = __float2half(emb[i]);
}

// Bh = fp16( wl[c,n]*W[n,kout]*1024 )  — transpose via smem tile
__global__ void prep_B(const float* __restrict__ W, const float* __restrict__ wl) {
    __shared__ float sW[32][33];
    int tx = threadIdx.x, ty = threadIdx.y;
    int n0 = blockIdx.x * 32, k0 = blockIdx.y * 32;
    sW[ty][tx] = W[(n0 + ty) * FDIM + (k0 + tx)];
    __syncthreads();
    float wv = sW[tx][ty];
    int oidx = (k0 + ty) * FDIM + (n0 + tx);
    for (int c = 0; c < CELLS; c++) {
        float v = 1024.f * wl[c * FDIM + n0 + tx] * wv;
        g_Bh[(size_t)c * FDIM * FDIM + oidx] = __float2half(v);
    }
}

// per-cell distinct-i0 compaction: flags + block scan. One block per cell, 1024 threads.
__global__ void __launch_bounds__(1024) compact_kernel(const int* __restrict__ index) {
    int c = blockIdx.x, t = threadIdx.x;
    __shared__ unsigned char flags[N_ENT];
    __shared__ int wsum[32];
    #pragma unroll
    for (int i = t; i < N_ENT; i += 1024) flags[i] = 0;
    __syncthreads();
    for (int p = t; p < PAIRS; p += 1024)
        flags[index[((size_t)c * PAIRS + p) * 2]] = 1;  // races benign (same value)
    __syncthreads();
    int f[4], s = 0;
    #pragma unroll
    for (int j = 0; j < 4; j++) { f[j] = flags[t * 4 + j]; s += f[j]; }
    int lane = t & 31, wid = t >> 5;
    int sc = s;
    #pragma unroll
    for (int o = 1; o < 32; o <<= 1) {
        int v = __shfl_up_sync(0xffffffffu, sc, o);
        if (lane >= o) sc += v;
    }
    if (lane == 31) wsum[wid] = sc;
    __syncthreads();
    if (wid == 0) {
        int v = wsum[lane];
        #pragma unroll
        for (int o = 1; o < 32; o <<= 1) {
            int u = __shfl_up_sync(0xffffffffu, v, o);
            if (lane >= o) v += u;
        }
        wsum[lane] = v;   // inclusive scan of warp totals
    }
    __syncthreads();
    int base = (wid > 0 ? wsum[wid - 1] : 0) + (sc - s);   // exclusive prefix
    #pragma unroll
    for (int j = 0; j < 4; j++) {
        if (f[j]) {
            int i = t * 4 + j;
            g_map[c * N_ENT + i] = base;
            g_list[c * N_ENT + base] = i;
            base++;
        }
    }
    if (t == 1023) g_cnt[c] = wsum[31];
}

// ---------------- GEMM: compacted-M fp16, XOR-swizzled smem, 2 CTAs/SM, 3-stage ---------
// CTA tile M=128, N=128, BK=64, 256 threads (8 warps 2Mx4N, warp tile 64x32).
// Runs at the measured structural HMMA rate (~13.4 cyc/mma/SMSP).
#define BK          64
#define NKC         (FDIM / BK)       // 8 chunks
#define A_TILE      (128 * 128)       // 16384
#define B_TILE      (128 * 128)       // 16384
#define A_OFF       0
#define B_OFF       (A_TILE)
#define BUF_BYTES   (A_TILE + B_TILE)       // 32768
#define NSTAGE      3
#define GEMM_SMEM   (NSTAGE * BUF_BYTES)    // 98304 -> 2 CTAs/SM
#define NTHREADS    256

__device__ __forceinline__ void load_buf(uint32_t smem_u, int stage, int kc, int tid,
                                         const int* srow, const char* bh) {
    uint32_t dbase = smem_u + stage * BUF_BYTES;
    #pragma unroll
    for (int i = 0; i < 4; i++) {
        int v = i * NTHREADS + tid;
        int row = v >> 3, seg = v & 7;
        const char* s = (const char*)g_Eh + (size_t)srow[row] * (FDIM * 2)
                        + (size_t)kc * (BK * 2) + seg * 16;
        cp_async16(dbase + A_OFF + row * 128 + ((seg ^ (row & 7)) << 4), s);
    }
    {
        const char* s = bh + (size_t)kc * (BK * 2);
        #pragma unroll
        for (int i = 0; i < 4; i++) {
            int v = i * NTHREADS + tid;
            int row = v >> 3, seg = v & 7;
            cp_async16(dbase + B_OFF + row * 128 + ((seg ^ (row & 7)) << 4),
                       s + (size_t)row * (FDIM * 2) + seg * 16);
        }
    }
}

__global__ void __launch_bounds__(NTHREADS, 2)
gemm_kernel(const float* __restrict__ wl, int c0) {
    extern __shared__ char smem[];
    __shared__ int srow[128];
    uint32_t smem_u = smem_to_u32(smem);

    const int tid = threadIdx.x;
    const int wid = tid >> 5, lane = tid & 31;
    const int warp_m = wid & 1;
    const int warp_n = wid >> 1;
    const int mt = blockIdx.x, nt = blockIdx.y, c = blockIdx.z + c0;

    const int cnt = __ldg(&g_cnt[c]);
    if (mt * 128 >= cnt) return;

    if (tid < 128) {
        int r = mt * 128 + tid;
        srow[tid] = __ldg(&g_list[c * N_ENT + (r < cnt ? r : mt * 128)]);
    }
    __syncthreads();

    const char* bh = (const char*)g_Bh + ((size_t)c * FDIM + nt * 128) * (FDIM * 2);

    float acc[4][4][4];
    #pragma unroll
    for (int i = 0; i < 4; i++)
        #pragma unroll
        for (int j = 0; j < 4; j++)
            #pragma unroll
            for (int q = 0; q < 4; q++) acc[i][j][q] = 0.f;

    const int lr = lane & 15;
    const int hsel = lane >> 4;
    const int sw = lr & 7;

    load_buf(smem_u, 0, 0, tid, srow, bh);
    CP_COMMIT();
    load_buf(smem_u, 1, 1, tid, srow, bh);
    CP_COMMIT();

    int stage = 0;
    for (int kc = 0; kc < NKC; kc++) {
        CP_WAIT(1);
        __syncthreads();
        if (kc + 2 < NKC) {
            int s2 = stage + 2; if (s2 >= NSTAGE) s2 -= NSTAGE;
            load_buf(smem_u, s2, kc + 2, tid, srow, bh);
            CP_COMMIT();
        } else {
            CP_COMMIT();
        }

        uint32_t base = smem_u + stage * BUF_BYTES;
        uint32_t aBase = base + A_OFF + (warp_m * 64 + lr) * 128;
        uint32_t bBase = base + B_OFF + (warp_n * 32 + lr) * 128;

        #pragma unroll
        for (int k16 = 0; k16 < BK / 16; k16++) {
            uint32_t cc = (uint32_t)(((k16 * 2 + hsel) ^ sw) << 4);
            uint32_t ah[4][4], bf[2][4];
            #pragma unroll
            for (int mi = 0; mi < 4; mi++)
                LDSM_X4(ah[mi], aBase + mi * (16 * 128) + cc);
            #pragma unroll
            for (int nj = 0; nj < 2; nj++)
                LDSM_X4(bf[nj], bBase + nj * (16 * 128) + cc);
            #pragma unroll
            for (int mi = 0; mi < 4; mi++)
                #pragma unroll
                for (int n = 0; n < 4; n++) {
                    int nj = n >> 1, hf = n & 1;
                    mma_f16(acc[mi][n], ah[mi], bf[nj][hf], bf[nj][hf + 2]);
                }
        }
        if (++stage >= NSTAGE) stage = 0;
    }

    // epilogue: T16[compact row] = fp16( acc * 2^-10 * wl[c,kout] * 2^6 )
    const int gid = lane >> 2, tq = lane & 3;
    const int row0 = mt * 128 + warp_m * 64 + gid;
    const int col0 = nt * 128 + warp_n * 32 + tq * 2;
    const float s_main = 64.0f / 1024.0f;
    #pragma unroll
    for (int n = 0; n < 4; n++) {
        int cg = col0 + n * 8;
        float w0 = __ldg(&wl[c * FDIM + cg]) * s_main;
        float w1 = __ldg(&wl[c * FDIM + cg + 1]) * s_main;
        #pragma unroll
        for (int mi = 0; mi < 4; mi++) {
            int r = row0 + mi * 16;
            __half* o0 = g_T + ((size_t)c * N_ENT + r) * FDIM + cg;
            __half* o1 = g_T + ((size_t)c * N_ENT + r + 8) * FDIM + cg;
            *(__half2*)o0 = __floats2half2_rn(acc[mi][n][0] * w0, acc[mi][n][1] * w1);
            *(__half2*)o1 = __floats2half2_rn(acc[mi][n][2] * w0, acc[mi][n][3] * w1);
        }
    }
}

// ---------------- gather-dot: out[c,p] = 2^-6 * dot(T16_c[map[i0],:], Eh[i1,:]) ---------
// 64-THREAD CTAs (2 warps x 4 pairs): CTA reg footprint ~2.4K -> fits in the ~3.5K regs
// free beside TWO resident gemm CTAs (2x256x121 = 62K of 64K) -> true co-residency.
#define GTHREADS 64

__global__ void __launch_bounds__(GTHREADS) gather_kernel(const int* __restrict__ index,
                                                          float* __restrict__ out, int c0) {
    int gw = (blockIdx.x * GTHREADS + threadIdx.x) >> 5;
    int lane = threadIdx.x & 31;
    int p0 = gw * 4;
    int c = p0 / PAIRS + c0, p = p0 % PAIRS;
    const uint4* ta[4];
    const uint4* tb[4];
    #pragma unroll
    for (int u = 0; u < 4; u++) {
        int2 ip = __ldg((const int2*)index + (size_t)c * PAIRS + p + u);
        int r0 = __ldg(&g_map[c * N_ENT + ip.x]);
        ta[u] = (const uint4*)(g_T + ((size_t)c * N_ENT + r0) * FDIM);
        tb[u] = (const uint4*)(g_Eh + (size_t)ip.y * FDIM);
    }
    float acc[4] = {0.f, 0.f, 0.f, 0.f};
    #pragma unroll
    for (int j = 0; j < 2; j++) {
        #pragma unroll
        for (int u = 0; u < 4; u++) {
            uint4 x = __ldg(ta[u] + lane + j * 32);
            uint4 y = __ldg(tb[u] + lane + j * 32);
            const uint32_t* xa = (const uint32_t*)&x;
            const uint32_t* ya = (const uint32_t*)&y;
            #pragma unroll
            for (int q = 0; q < 4; q++) {
                float2 fx = __half22float2(*(const __half2*)&xa[q]);
                float2 fy = __half22float2(*(const __half2*)&ya[q]);
                acc[u] += fx.x * fy.x + fx.y * fy.y;
            }
        }
    }
    #pragma unroll
    for (int o = 16; o; o >>= 1)
        #pragma unroll
        for (int u = 0; u < 4; u++)
            acc[u] += __shfl_xor_sync(0xffffffffu, acc[u], o);
    if (lane == 0) {
        const float s = 1.0f / 64.0f;
        #pragma unroll
        for (int u = 0; u < 4; u++)
            out[(size_t)c * PAIRS + p + u] = acc[u] * s;
    }
}

// ---------------- launch: 5 gemm groups alternating 2 streams; gathers co-resident -------
#define NGROUP 5

extern "C" void kernel_launch(void* const* d_in, const int* in_sizes, int n_in,
                              void* d_out, int out_size) {
    const float* emb   = (const float*)d_in[0];   // [4096, 512] f32
    const int*   index = (const int*)d_in[1];     // [39, 8192, 2] i32
    const float* W     = (const float*)d_in[2];   // [512, 512] f32
    const float* wl    = (const float*)d_in[3];   // [39, 512] f32
    float* out = (float*)d_out;                   // [39, 8192] f32

    static cudaStream_t sA = nullptr, sB = nullptr, sG = nullptr;
    static cudaEvent_t evFork, evPrepE, evPrepB, evCmp;
    static cudaEvent_t evGemm[NGROUP], evJA, evJB, evJG;
    if (sA == nullptr) {
        cudaStreamCreateWithFlags(&sA, cudaStreamNonBlocking);
        cudaStreamCreateWithFlags(&sB, cudaStreamNonBlocking);
        cudaStreamCreateWithFlags(&sG, cudaStreamNonBlocking);
        cudaEventCreateWithFlags(&evFork, cudaEventDisableTiming);
        cudaEventCreateWithFlags(&evPrepE, cudaEventDisableTiming);
        cudaEventCreateWithFlags(&evPrepB, cudaEventDisableTiming);
        cudaEventCreateWithFlags(&evCmp, cudaEventDisableTiming);
        for (int g = 0; g < NGROUP; g++)
            cudaEventCreateWithFlags(&evGemm[g], cudaEventDisableTiming);
        cudaEventCreateWithFlags(&evJA, cudaEventDisableTiming);
        cudaEventCreateWithFlags(&evJB, cudaEventDisableTiming);
        cudaEventCreateWithFlags(&evJG, cudaEventDisableTiming);
        cudaFuncSetAttribute(gemm_kernel, cudaFuncAttributeMaxDynamicSharedMemorySize, GEMM_SMEM);
    }

    // Fork side streams from the capture (default) stream.
    cudaEventRecord(evFork, 0);
    cudaStreamWaitEvent(sA, evFork, 0);
    cudaStreamWaitEvent(sB, evFork, 0);
    cudaStreamWaitEvent(sG, evFork, 0);

    // Independent preps run concurrently.
    prep_E<<<1024, 256, 0, sA>>>(emb);
    cudaEventRecord(evPrepE, sA);
    prep_B<<<dim3(FDIM / 32, FDIM / 32), dim3(32, 32), 0, sB>>>(W, wl);
    cudaEventRecord(evPrepB, sB);
    compact_kernel<<<CELLS, 1024, 0, sG>>>(index);
    cudaEventRecord(evCmp, sG);

    // Both gemm streams need all three preps.
    cudaStreamWaitEvent(sA, evPrepB, 0); cudaStreamWaitEvent(sA, evCmp, 0);
    cudaStreamWaitEvent(sB, evPrepE, 0); cudaStreamWaitEvent(sB, evCmp, 0);

    // Gemm groups alternate sA/sB (tails overlap next ramp); gathers on sG with
    // 64-thread CTAs co-resident beside gemm CTAs.
    int c0 = 0;
    for (int g = 0; g < NGROUP; g++) {
        int nc = (g < NGROUP - 1) ? 8 : (CELLS - 8 * (NGROUP - 1));   // 8,8,8,8,7
        cudaStream_t sg = (g & 1) ? sB : sA;
        gemm_kernel<<<dim3(N_ENT / 128, FDIM / 128, nc), NTHREADS, GEMM_SMEM, sg>>>(wl, c0);
        cudaEventRecord(evGemm[g], sg);
        cudaStreamWaitEvent(sG, evGemm[g], 0);
        gather_kernel<<<nc * (PAIRS / 8), GTHREADS, 0, sG>>>(index, out, c0);
        c0 += nc;
    }

    // Rejoin everything onto the capture stream.
    cudaEventRecord(evJA, sA); cudaStreamWaitEvent(0, evJA, 0);
    cudaEventRecord(evJB, sB); cudaStreamWaitEvent(0, evJB, 0);
    cudaEventRecord(evJG, sG); cudaStreamWaitEvent(0, evJG, 0);
}